// round 14
// baseline (speedup 1.0000x reference)
#include <cuda_runtime.h>
#include <math.h>

#define NSI 120
#define NS2 (NSI*NSI)      // 14400
#define NS3 (NSI*NSI*NSI)  // 1728000
#define RKY 61             // ky 0..60 (Hermitian half, y axis)
#define NROWS (NSI*RKY)    // 7320 (kx,ky) rows
#define ALPHA_F 1.0f
#define PI_D 3.14159265358979323846

typedef unsigned long long u64;

// ---------------- scratch (static device globals; no allocation) ----------------
__device__ __align__(16) float  g_mesh[NS3];
__device__ __align__(16) float2 g_buf1[NSI*RKY*NSI];   // [(x*61+ky)*120+z]
__device__ __align__(16) float2 g_buf2[NSI*NROWS];     // z-major: [z*7320 + kx*61+ky]
__device__ float  g_invc[9];   // inv(box)[i][j] at [i*3+j]
__device__ double g_vol;
__device__ double g_acc[3];    // [0]=Sum |S|^2 G, [1]=sum q, [2]=sum q^2
__device__ float2 g_tw[NSI];   // exp(-2*pi*i*t/120)

// ---------------- packed f32x2 helpers ----------------
__device__ __forceinline__ u64 pk2(float x, float y) {
    u64 r; asm("mov.b64 %0, {%1, %2};" : "=l"(r) : "f"(x), "f"(y)); return r;
}
__device__ __forceinline__ void upk2(u64 v, float& x, float& y) {
    asm("mov.b64 {%0, %1}, %2;" : "=f"(x), "=f"(y) : "l"(v));
}
__device__ __forceinline__ void fma2(u64& d, u64 a, u64 b) {
    asm("fma.rn.f32x2 %0, %1, %2, %3;" : "=l"(d) : "l"(a), "l"(b), "l"(d));
}

// ---------------- vector global reductions (sm_90+) ----------------
__device__ __forceinline__ void red2(float* p, float a, float b) {
    asm volatile("red.global.add.v2.f32 [%0], {%1, %2};"
                 :: "l"(p), "f"(a), "f"(b) : "memory");
}
__device__ __forceinline__ void red4(float* p, float a, float b, float c, float d) {
    asm volatile("red.global.add.v4.f32 [%0], {%1, %2, %3, %4};"
                 :: "l"(p), "f"(a), "f"(b), "f"(c), "f"(d) : "memory");
}

// ---------------- setup ----------------
__global__ void setup_kernel(const float* __restrict__ box) {
    int t = threadIdx.x;
    if (t < NSI) {
        double ang = -2.0 * PI_D * (double)t / (double)NSI;
        g_tw[t] = make_float2((float)cos(ang), (float)sin(ang));
    }
    if (t == 0) {
        double b[9];
        for (int i = 0; i < 9; i++) b[i] = (double)box[i];
        double c00 =  (b[4]*b[8] - b[5]*b[7]);
        double c01 = -(b[3]*b[8] - b[5]*b[6]);
        double c02 =  (b[3]*b[7] - b[4]*b[6]);
        double c10 = -(b[1]*b[8] - b[2]*b[7]);
        double c11 =  (b[0]*b[8] - b[2]*b[6]);
        double c12 = -(b[0]*b[7] - b[1]*b[6]);
        double c20 =  (b[1]*b[5] - b[2]*b[4]);
        double c21 = -(b[0]*b[5] - b[2]*b[3]);
        double c22 =  (b[0]*b[4] - b[1]*b[3]);
        double det = b[0]*c00 + b[1]*c01 + b[2]*c02;
        g_invc[0] = (float)(c00/det); g_invc[1] = (float)(c10/det); g_invc[2] = (float)(c20/det);
        g_invc[3] = (float)(c01/det); g_invc[4] = (float)(c11/det); g_invc[5] = (float)(c21/det);
        g_invc[6] = (float)(c02/det); g_invc[7] = (float)(c12/det); g_invc[8] = (float)(c22/det);
        g_vol = fabs(det);
        g_acc[0] = 0.0; g_acc[1] = 0.0; g_acc[2] = 0.0;
    }
}

__global__ void zero_mesh_kernel() {
    int i = blockIdx.x * blockDim.x + threadIdx.x;
    float4* p = (float4*)g_mesh;
    if (i < NS3/4) p[i] = make_float4(0.f, 0.f, 0.f, 0.f);
}

// ---------------- order-6 Lagrange weights, nodes t_j = j - 2.5 ----------------
__device__ __forceinline__ void lag6(float x, float* w) {
    float d0 = x + 2.5f, d1 = x + 1.5f, d2 = x + 0.5f;
    float d3 = x - 0.5f, d4 = x - 1.5f, d5 = x - 2.5f;
    float p1 = d0, p2 = p1*d1, p3 = p2*d2, p4 = p3*d3, p5 = p4*d4;
    float s4 = d5, s3 = s4*d4, s2 = s3*d3, s1 = s2*d2, s0 = s1*d1;
    w[0] = s0      * (-1.f/120.f);
    w[1] = p1 * s1 * ( 1.f/24.f);
    w[2] = p2 * s2 * (-1.f/12.f);
    w[3] = p3 * s3 * ( 1.f/12.f);
    w[4] = p4 * s4 * (-1.f/24.f);
    w[5] = p5      * ( 1.f/120.f);
}

__device__ __forceinline__ int wrap120(int v) {
    return (v < 0) ? v + NSI : ((v >= NSI) ? v - NSI : v);
}

// ---------------- spread: one thread per atom, vector reductions --------------
__global__ void spread_kernel(const float* __restrict__ coords,
                              const float* __restrict__ charges, int n) {
    int i = blockIdx.x * blockDim.x + threadIdx.x;
    float q = 0.f;
    float wx[6], wy[6], wz[6];
    int gx[6], gy[6], gz[6];
    int z0w = 0;
    bool act = (i < n);
    if (act) {
        float c0 = coords[3*i], c1 = coords[3*i+1], c2 = coords[3*i+2];
        q = charges[i];
        float fx = c0*g_invc[0] + c1*g_invc[3] + c2*g_invc[6];
        float fy = c0*g_invc[1] + c1*g_invc[4] + c2*g_invc[7];
        float fz = c0*g_invc[2] + c1*g_invc[5] + c2*g_invc[8];
        float px = fx * (float)NSI, py = fy * (float)NSI, pz = fz * (float)NSI;
        float i0x = floorf(px), i0y = floorf(py), i0z = floorf(pz);
        lag6(px - i0x - 0.5f, wx);
        lag6(py - i0y - 0.5f, wy);
        lag6(pz - i0z - 0.5f, wz);
        int ix = (int)i0x, iy = (int)i0y, iz = (int)i0z;
        #pragma unroll
        for (int a = 0; a < 6; a++) {
            gx[a] = wrap120(ix + a - 2);
            gy[a] = wrap120(iy + a - 2);
            gz[a] = wrap120(iz + a - 2);
        }
        z0w = gz[0];
    }
    double dq = (double)q, dq2 = (double)q * (double)q;
    #pragma unroll
    for (int o = 16; o; o >>= 1) {
        dq  += __shfl_down_sync(0xffffffffu, dq,  o);
        dq2 += __shfl_down_sync(0xffffffffu, dq2, o);
    }
    if ((threadIdx.x & 31) == 0) {
        atomicAdd(&g_acc[1], dq);
        atomicAdd(&g_acc[2], dq2);
    }
    if (!act) return;

    bool zcontig = (z0w <= NSI - 6);    // 6 consecutive z cells, no wrap
    int zmod = z0w & 3;                 // uniform over the whole atom

    #pragma unroll
    for (int a = 0; a < 6; a++) {
        int rowx = gx[a] * NS2;
        float wq = wx[a] * q;
        #pragma unroll
        for (int b = 0; b < 6; b++) {
            int row = rowx + gy[b] * NSI;
            float wxy = wq * wy[b];
            float v0 = wxy*wz[0], v1 = wxy*wz[1], v2 = wxy*wz[2];
            float v3 = wxy*wz[3], v4 = wxy*wz[4], v5 = wxy*wz[5];
            if (zcontig) {
                float* p = g_mesh + row + z0w;
                if (zmod == 0) {
                    red4(p, v0, v1, v2, v3);
                    red2(p + 4, v4, v5);
                } else if (zmod == 2) {
                    red2(p, v0, v1);
                    red4(p + 2, v2, v3, v4, v5);
                } else if (zmod == 3) {
                    atomicAdd(p, v0);
                    red4(p + 1, v1, v2, v3, v4);
                    atomicAdd(p + 5, v5);
                } else { // zmod == 1: zero-padded aligned pair (z0<=113 here)
                    red4(p - 1, 0.f, v0, v1, v2);
                    red4(p + 3, v3, v4, v5, 0.f);
                }
            } else {
                atomicAdd(&g_mesh[row + gz[0]], v0);
                atomicAdd(&g_mesh[row + gz[1]], v1);
                atomicAdd(&g_mesh[row + gz[2]], v2);
                atomicAdd(&g_mesh[row + gz[3]], v3);
                atomicAdd(&g_mesh[row + gz[4]], v4);
                atomicAdd(&g_mesh[row + gz[5]], v5);
            }
        }
    }
}

// ---------------- pass A: y-DFT (real->complex), 16 ky per block --------------
// grid (4 ky-chunks of 16, 120 x), block 128; thread = z (coalesced).
// mesh read once per chunk: 4x6.9MB = 27MB L2 traffic (was 55).
__global__ void __launch_bounds__(128) passA_kernel() {
    __shared__ __align__(16) u64 tw16[60 * 16];   // packed (cos,sin); y=0 unused
    int kyc = blockIdx.x;
    int x   = blockIdx.y;
    int tid = threadIdx.x;
    for (int i = tid; i < 60 * 16; i += 128) {
        int y = i >> 4, c = i & 15;
        int ky = kyc * 16 + c;
        float2 t = g_tw[(ky * y) % NSI];
        tw16[i] = pk2(t.x, t.y);
    }
    __syncthreads();
    if (tid < NSI) {
        int z = tid;
        const float* mrow = g_mesh + x * NS2 + z;
        u64 acc[16];
        #pragma unroll
        for (int c = 0; c < 16; c++) acc[c] = pk2(0.f, 0.f);
        float v0  = mrow[0];
        float v60 = mrow[60 * NSI];
        for (int yp = 1; yp < 60; yp++) {
            float a = mrow[yp * NSI];
            float b = mrow[(NSI - yp) * NSI];
            u64 uw = pk2(a + b, a - b);
            const ulonglong2* t = (const ulonglong2*)&tw16[yp * 16];
            #pragma unroll
            for (int j = 0; j < 8; j++) {
                ulonglong2 tv = t[j];
                fma2(acc[2*j  ], uw, tv.x);
                fma2(acc[2*j+1], uw, tv.y);
            }
        }
        #pragma unroll
        for (int c = 0; c < 16; c++) {
            int ky = kyc * 16 + c;
            if (ky < RKY) {
                float ax, ay; upk2(acc[c], ax, ay);
                float sgn = (ky & 1) ? -1.f : 1.f;
                float sx = ax + v0 + sgn * v60;
                g_buf1[(x * RKY + ky) * NSI + z] = make_float2(sx, ay);
            }
        }
    }
}

// ---------------- pass B: x-DFT (complex), 16 kx per block --------------------
// grid (8 kx-chunks of 16, 61 ky), block 128; thread = z.
// buf1 read once per chunk: 8x13.9MB = 111MB L2 traffic (was 209).
__global__ void __launch_bounds__(128) passB_kernel() {
    __shared__ __align__(16) u64 tw16[60 * 16 * 2];  // per (x,kx): (c,c), (-s,s)
    int kxc = blockIdx.x;
    int ky  = blockIdx.y;
    int tid = threadIdx.x;
    for (int i = tid; i < 60 * 16; i += 128) {
        int xv = i >> 4, c = i & 15;
        int kx = kxc * 16 + c;
        float2 t = g_tw[(kx * xv) % NSI];   // kx>=120 harmless (guarded at store)
        tw16[2*i]   = pk2(t.x, t.x);
        tw16[2*i+1] = pk2(-t.y, t.y);
    }
    __syncthreads();
    if (tid < NSI) {
        int z = tid;
        u64 acc[16];
        #pragma unroll
        for (int c = 0; c < 16; c++) acc[c] = pk2(0.f, 0.f);
        const float2* col = g_buf1 + ky * NSI + z;   // stride over x = RKY*NSI
        float2 v0  = col[0];
        float2 v60 = col[60 * (RKY * NSI)];
        for (int xp = 1; xp < 60; xp++) {
            float2 a = col[xp * (RKY * NSI)];
            float2 b = col[(NSI - xp) * (RKY * NSI)];
            u64 u1 = pk2(a.x + b.x, a.y + b.y);      // (ux, uy)
            u64 u2 = pk2(a.y - b.y, a.x - b.x);      // (wy, wx)
            const ulonglong2* t = (const ulonglong2*)&tw16[xp * 32];
            #pragma unroll
            for (int c = 0; c < 16; c++) {
                ulonglong2 tv = t[c];
                fma2(acc[c], u1, tv.x);   // += (c*ux, c*uy)
                fma2(acc[c], u2, tv.y);   // += (-s*wy, s*wx)
            }
        }
        #pragma unroll
        for (int c = 0; c < 16; c++) {
            int kx = kxc * 16 + c;
            if (kx < NSI) {
                float ax, ay; upk2(acc[c], ax, ay);
                float sgn = (kx & 1) ? -1.f : 1.f;
                float sx = ax + v0.x + sgn * v60.x;
                float sy = ay + v0.y + sgn * v60.y;
                g_buf2[z * NROWS + kx * RKY + ky] = make_float2(sx, sy);
            }
        }
    }
}

// ---------------- pass C: z-DFT fused with Sum w*|S|^2*G, 20 kz per block -----
// grid (6 kz-chunks of 20, 58 row-blocks), block 128; thread = row.
// buf2 read once per chunk: 6x7MB = 42MB L2 traffic (was 84).
__global__ void __launch_bounds__(128) passC_kernel() {
    __shared__ __align__(16) u64 tw20[60 * 20 * 2];  // per (z,kz): (c,c), (-s,s)
    __shared__ double red[4];
    int kzc = blockIdx.x;          // kz = kzc*20 + c
    int r   = blockIdx.y * 128 + threadIdx.x;
    int tid = threadIdx.x;
    for (int i = tid; i < 60 * 20; i += 128) {
        int z = i / 20, c = i % 20;
        int kz = kzc * 20 + c;
        float2 t = g_tw[(kz * z) % NSI];
        tw20[2*i]   = pk2(t.x, t.x);
        tw20[2*i+1] = pk2(-t.y, t.y);
    }
    __syncthreads();
    bool act = (r < NROWS);
    u64 acc[20];
    #pragma unroll
    for (int c = 0; c < 20; c++) acc[c] = pk2(0.f, 0.f);
    float2 v0 = make_float2(0.f, 0.f), v60 = make_float2(0.f, 0.f);
    if (act) {
        const float2* col = g_buf2 + r;   // stride over z = NROWS
        v0  = col[0];
        v60 = col[60 * NROWS];
        for (int zp = 1; zp < 60; zp++) {
            float2 a = col[zp * NROWS];
            float2 b = col[(NSI - zp) * NROWS];
            u64 u1 = pk2(a.x + b.x, a.y + b.y);
            u64 u2 = pk2(a.y - b.y, a.x - b.x);
            const ulonglong2* t = (const ulonglong2*)&tw20[zp * 40];
            #pragma unroll
            for (int c = 0; c < 20; c++) {
                ulonglong2 tv = t[c];
                fma2(acc[c], u1, tv.x);
                fma2(acc[c], u2, tv.y);
            }
        }
    }
    double contrib = 0.0;
    if (act) {
        int kx = r / RKY, ky = r % RKY;
        int mx = (kx < 60) ? kx : kx - NSI;
        int my = (ky < 60) ? ky : ky - NSI;   // ky==60 -> -60
        float wgt = (ky == 0 || ky == 60) ? 1.0f : 2.0f;
        float fmx = (float)mx, fmy = (float)my;
        const float twopi = 6.28318530717958647692f;
        #pragma unroll
        for (int c = 0; c < 20; c++) {
            int kz = kzc * 20 + c;
            float sgn = (kz & 1) ? -1.f : 1.f;
            float ax, ay; upk2(acc[c], ax, ay);
            float sx = ax + v0.x + sgn * v60.x;
            float sy = ay + v0.y + sgn * v60.y;
            int mz = (kz < 60) ? kz : kz - NSI;
            float fmz = (float)mz;
            float k0 = twopi * (fmx * g_invc[0] + fmy * g_invc[1] + fmz * g_invc[2]);
            float k1 = twopi * (fmx * g_invc[3] + fmy * g_invc[4] + fmz * g_invc[5]);
            float k2 = twopi * (fmx * g_invc[6] + fmy * g_invc[7] + fmz * g_invc[8]);
            float ksq = k0*k0 + k1*k1 + k2*k2;
            float G = 0.f;
            if (ksq > 0.f)
                G = 4.f * (float)PI_D * expf(-0.5f * ALPHA_F * ALPHA_F * ksq) / ksq;
            G *= wgt;
            contrib += (double)G * ((double)sx * (double)sx +
                                    (double)sy * (double)sy);
        }
    }
    #pragma unroll
    for (int o = 16; o; o >>= 1)
        contrib += __shfl_down_sync(0xffffffffu, contrib, o);
    if ((tid & 31) == 0) red[tid >> 5] = contrib;
    __syncthreads();
    if (tid == 0) {
        double s = red[0] + red[1] + red[2] + red[3];
        atomicAdd(&g_acc[0], s);
    }
}

// ---------------- finalize ----------------
__global__ void final_kernel(float* out) {
    double V  = g_vol;
    double A  = g_acc[0];
    double qs = g_acc[1];
    double q2 = g_acc[2];
    double E = 0.5 * ( A / V
                     - sqrt(2.0 / PI_D) / (double)ALPHA_F * q2
                     - 2.0 * PI_D * (double)(ALPHA_F * ALPHA_F) * qs * qs / V );
    out[0] = (float)E;
}

extern "C" void kernel_launch(void* const* d_in, const int* in_sizes, int n_in,
                              void* d_out, int out_size) {
    const float* coords  = (const float*)d_in[0];
    const float* box     = (const float*)d_in[1];
    const float* charges = (const float*)d_in[2];
    int n = in_sizes[2];   // N_ATOMS

    setup_kernel<<<1, 128>>>(box);
    zero_mesh_kernel<<<(NS3/4 + 255)/256, 256>>>();
    spread_kernel<<<(n + 127)/128, 128>>>(coords, charges, n);
    passA_kernel<<<dim3(4, NSI), 128>>>();
    passB_kernel<<<dim3(8, RKY), 128>>>();
    passC_kernel<<<dim3(6, (NROWS + 127)/128), 128>>>();
    final_kernel<<<1, 1>>>((float*)d_out);
}

// round 15
// speedup vs baseline: 1.1991x; 1.1991x over previous
#include <cuda_runtime.h>
#include <math.h>

#define NSI 120
#define NS2 (NSI*NSI)      // 14400
#define NS3 (NSI*NSI*NSI)  // 1728000
#define RKY 61             // ky 0..60 (Hermitian half, y axis)
#define ALPHA_F 1.0f
#define PI_D 3.14159265358979323846

typedef unsigned long long u64;

// ---------------- scratch (static device globals; no allocation) ----------------
__device__ __align__(16) float  g_mesh[NS3];
__device__ __align__(16) float2 g_buf1[NSI*RKY*NSI];   // [(x*61+ky)*120+z]
__device__ float  g_invc[9];   // inv(box)[i][j] at [i*3+j]
__device__ double g_vol;
__device__ double g_acc[3];    // [0]=Sum |S|^2 G, [1]=sum q, [2]=sum q^2
__device__ float2 g_tw[NSI];   // exp(-2*pi*i*t/120)

// ---------------- packed f32x2 helpers ----------------
__device__ __forceinline__ u64 pk2(float x, float y) {
    u64 r; asm("mov.b64 %0, {%1, %2};" : "=l"(r) : "f"(x), "f"(y)); return r;
}
__device__ __forceinline__ void upk2(u64 v, float& x, float& y) {
    asm("mov.b64 {%0, %1}, %2;" : "=f"(x), "=f"(y) : "l"(v));
}
__device__ __forceinline__ void fma2(u64& d, u64 a, u64 b) {
    asm("fma.rn.f32x2 %0, %1, %2, %3;" : "=l"(d) : "l"(a), "l"(b), "l"(d));
}

// ---------------- vector global reductions (sm_90+) ----------------
__device__ __forceinline__ void red2(float* p, float a, float b) {
    asm volatile("red.global.add.v2.f32 [%0], {%1, %2};"
                 :: "l"(p), "f"(a), "f"(b) : "memory");
}
__device__ __forceinline__ void red4(float* p, float a, float b, float c, float d) {
    asm volatile("red.global.add.v4.f32 [%0], {%1, %2, %3, %4};"
                 :: "l"(p), "f"(a), "f"(b), "f"(c), "f"(d) : "memory");
}

// ---------------- setup ----------------
__global__ void setup_kernel(const float* __restrict__ box) {
    int t = threadIdx.x;
    if (t < NSI) {
        double ang = -2.0 * PI_D * (double)t / (double)NSI;
        g_tw[t] = make_float2((float)cos(ang), (float)sin(ang));
    }
    if (t == 0) {
        double b[9];
        for (int i = 0; i < 9; i++) b[i] = (double)box[i];
        double c00 =  (b[4]*b[8] - b[5]*b[7]);
        double c01 = -(b[3]*b[8] - b[5]*b[6]);
        double c02 =  (b[3]*b[7] - b[4]*b[6]);
        double c10 = -(b[1]*b[8] - b[2]*b[7]);
        double c11 =  (b[0]*b[8] - b[2]*b[6]);
        double c12 = -(b[0]*b[7] - b[1]*b[6]);
        double c20 =  (b[1]*b[5] - b[2]*b[4]);
        double c21 = -(b[0]*b[5] - b[2]*b[3]);
        double c22 =  (b[0]*b[4] - b[1]*b[3]);
        double det = b[0]*c00 + b[1]*c01 + b[2]*c02;
        g_invc[0] = (float)(c00/det); g_invc[1] = (float)(c10/det); g_invc[2] = (float)(c20/det);
        g_invc[3] = (float)(c01/det); g_invc[4] = (float)(c11/det); g_invc[5] = (float)(c21/det);
        g_invc[6] = (float)(c02/det); g_invc[7] = (float)(c12/det); g_invc[8] = (float)(c22/det);
        g_vol = fabs(det);
        g_acc[0] = 0.0; g_acc[1] = 0.0; g_acc[2] = 0.0;
    }
}

__global__ void zero_mesh_kernel() {
    int i = blockIdx.x * blockDim.x + threadIdx.x;
    float4* p = (float4*)g_mesh;
    if (i < NS3/4) p[i] = make_float4(0.f, 0.f, 0.f, 0.f);
}

// ---------------- order-6 Lagrange weights, nodes t_j = j - 2.5 ----------------
__device__ __forceinline__ void lag6(float x, float* w) {
    float d0 = x + 2.5f, d1 = x + 1.5f, d2 = x + 0.5f;
    float d3 = x - 0.5f, d4 = x - 1.5f, d5 = x - 2.5f;
    float p1 = d0, p2 = p1*d1, p3 = p2*d2, p4 = p3*d3, p5 = p4*d4;
    float s4 = d5, s3 = s4*d4, s2 = s3*d3, s1 = s2*d2, s0 = s1*d1;
    w[0] = s0      * (-1.f/120.f);
    w[1] = p1 * s1 * ( 1.f/24.f);
    w[2] = p2 * s2 * (-1.f/12.f);
    w[3] = p3 * s3 * ( 1.f/12.f);
    w[4] = p4 * s4 * (-1.f/24.f);
    w[5] = p5      * ( 1.f/120.f);
}

__device__ __forceinline__ int wrap120(int v) {
    return (v < 0) ? v + NSI : ((v >= NSI) ? v - NSI : v);
}

// ---------------- spread: one thread per atom, vector reductions --------------
__global__ void spread_kernel(const float* __restrict__ coords,
                              const float* __restrict__ charges, int n) {
    int i = blockIdx.x * blockDim.x + threadIdx.x;
    float q = 0.f;
    float wx[6], wy[6], wz[6];
    int gx[6], gy[6], gz[6];
    int z0w = 0;
    bool act = (i < n);
    if (act) {
        float c0 = coords[3*i], c1 = coords[3*i+1], c2 = coords[3*i+2];
        q = charges[i];
        float fx = c0*g_invc[0] + c1*g_invc[3] + c2*g_invc[6];
        float fy = c0*g_invc[1] + c1*g_invc[4] + c2*g_invc[7];
        float fz = c0*g_invc[2] + c1*g_invc[5] + c2*g_invc[8];
        float px = fx * (float)NSI, py = fy * (float)NSI, pz = fz * (float)NSI;
        float i0x = floorf(px), i0y = floorf(py), i0z = floorf(pz);
        lag6(px - i0x - 0.5f, wx);
        lag6(py - i0y - 0.5f, wy);
        lag6(pz - i0z - 0.5f, wz);
        int ix = (int)i0x, iy = (int)i0y, iz = (int)i0z;
        #pragma unroll
        for (int a = 0; a < 6; a++) {
            gx[a] = wrap120(ix + a - 2);
            gy[a] = wrap120(iy + a - 2);
            gz[a] = wrap120(iz + a - 2);
        }
        z0w = gz[0];
    }
    double dq = (double)q, dq2 = (double)q * (double)q;
    #pragma unroll
    for (int o = 16; o; o >>= 1) {
        dq  += __shfl_down_sync(0xffffffffu, dq,  o);
        dq2 += __shfl_down_sync(0xffffffffu, dq2, o);
    }
    if ((threadIdx.x & 31) == 0) {
        atomicAdd(&g_acc[1], dq);
        atomicAdd(&g_acc[2], dq2);
    }
    if (!act) return;

    bool zcontig = (z0w <= NSI - 6);    // 6 consecutive z cells, no wrap
    int zmod = z0w & 3;                 // uniform over the whole atom

    #pragma unroll
    for (int a = 0; a < 6; a++) {
        int rowx = gx[a] * NS2;
        float wq = wx[a] * q;
        #pragma unroll
        for (int b = 0; b < 6; b++) {
            int row = rowx + gy[b] * NSI;
            float wxy = wq * wy[b];
            float v0 = wxy*wz[0], v1 = wxy*wz[1], v2 = wxy*wz[2];
            float v3 = wxy*wz[3], v4 = wxy*wz[4], v5 = wxy*wz[5];
            if (zcontig) {
                float* p = g_mesh + row + z0w;
                if (zmod == 0) {
                    red4(p, v0, v1, v2, v3);
                    red2(p + 4, v4, v5);
                } else if (zmod == 2) {
                    red2(p, v0, v1);
                    red4(p + 2, v2, v3, v4, v5);
                } else if (zmod == 3) {
                    atomicAdd(p, v0);
                    red4(p + 1, v1, v2, v3, v4);
                    atomicAdd(p + 5, v5);
                } else { // zmod == 1: zero-padded aligned pair (z0<=113 here)
                    red4(p - 1, 0.f, v0, v1, v2);
                    red4(p + 3, v3, v4, v5, 0.f);
                }
            } else {
                atomicAdd(&g_mesh[row + gz[0]], v0);
                atomicAdd(&g_mesh[row + gz[1]], v1);
                atomicAdd(&g_mesh[row + gz[2]], v2);
                atomicAdd(&g_mesh[row + gz[3]], v3);
                atomicAdd(&g_mesh[row + gz[4]], v4);
                atomicAdd(&g_mesh[row + gz[5]], v5);
            }
        }
    }
}

// ---------------- pass A: DFT along y (real -> complex), ky in [0,60] ---------
// exact champion version. grid (8 ky-chunks of 8, 120 x), block 128.
__global__ void __launch_bounds__(128) passA_kernel() {
    __shared__ __align__(16) u64 tw8[60 * 8];   // packed (cos,sin); y=0 unused
    int kyc = blockIdx.x;
    int x   = blockIdx.y;
    int tid = threadIdx.x;
    for (int i = tid; i < 60 * 8; i += 128) {
        int y = i >> 3, c = i & 7;
        int ky = kyc * 8 + c;
        float2 t = g_tw[(ky * y) % NSI];
        tw8[i] = pk2(t.x, t.y);
    }
    __syncthreads();
    if (tid < NSI) {
        int z = tid;
        const float* mrow = g_mesh + x * NS2 + z;
        u64 acc[8];
        #pragma unroll
        for (int c = 0; c < 8; c++) acc[c] = pk2(0.f, 0.f);
        float v0  = mrow[0];
        float v60 = mrow[60 * NSI];
        for (int yp = 1; yp < 60; yp++) {
            float a = mrow[yp * NSI];
            float b = mrow[(NSI - yp) * NSI];
            u64 uw = pk2(a + b, a - b);
            const ulonglong2* t = (const ulonglong2*)&tw8[yp * 8];
            #pragma unroll
            for (int j = 0; j < 4; j++) {
                ulonglong2 tv = t[j];
                fma2(acc[2*j  ], uw, tv.x);
                fma2(acc[2*j+1], uw, tv.y);
            }
        }
        #pragma unroll
        for (int c = 0; c < 8; c++) {
            int ky = kyc * 8 + c;
            if (ky < RKY) {
                float ax, ay; upk2(acc[c], ax, ay);
                float sgn = (ky & 1) ? -1.f : 1.f;
                float sx = ax + v0 + sgn * v60;
                g_buf1[(x * RKY + ky) * NSI + z] = make_float2(sx, ay);
            }
        }
    }
}

// ---------------- fused pass B+C: x-DFT then in-block z-DFT + G|S|^2 reduce ---
// grid (15 kx-chunks of 8, 61 ky), block 128; thread = z for x-DFT, = kz after.
__global__ void __launch_bounds__(128) passBC_kernel() {
    __shared__ __align__(16) u64 tw8[60 * 8 * 2];    // per (x,kx): (c,c), (-s,s)
    __shared__ __align__(8)  float2 Sraw[8 * NSI];   // [c*120 + z]
    __shared__ __align__(8)  float2 fu[8 * 60];      // (ax+bx, ay+by) per (c,zp)
    __shared__ __align__(8)  float2 fw[8 * 60];      // (ay-by, ax-bx) per (c,zp)
    __shared__ __align__(8)  float2 tws[NSI];        // g_tw copy
    __shared__ double red[4];
    int kxc = blockIdx.x;
    int ky  = blockIdx.y;
    int tid = threadIdx.x;
    for (int i = tid; i < 60 * 8; i += 128) {
        int xv = i >> 3, c = i & 7;
        int kx = kxc * 8 + c;
        float2 t = g_tw[(kx * xv) % NSI];
        tw8[2*i]   = pk2(t.x, t.x);
        tw8[2*i+1] = pk2(-t.y, t.y);
    }
    if (tid < NSI) tws[tid] = g_tw[tid];
    __syncthreads();

    // ---- stage 1: x-DFT (exact champion passB arithmetic), result -> Sraw ----
    if (tid < NSI) {
        int z = tid;
        u64 acc[8];
        #pragma unroll
        for (int c = 0; c < 8; c++) acc[c] = pk2(0.f, 0.f);
        const float2* col = g_buf1 + ky * NSI + z;   // stride over x = RKY*NSI
        float2 v0  = col[0];
        float2 v60 = col[60 * (RKY * NSI)];
        for (int xp = 1; xp < 60; xp++) {
            float2 a = col[xp * (RKY * NSI)];
            float2 b = col[(NSI - xp) * (RKY * NSI)];
            u64 u1 = pk2(a.x + b.x, a.y + b.y);      // (ux, uy)
            u64 u2 = pk2(a.y - b.y, a.x - b.x);      // (wy, wx)
            const ulonglong2* t = (const ulonglong2*)&tw8[xp * 16];
            #pragma unroll
            for (int c = 0; c < 8; c++) {
                ulonglong2 tv = t[c];
                fma2(acc[c], u1, tv.x);   // += (c*ux, c*uy)
                fma2(acc[c], u2, tv.y);   // += (-s*wy, s*wx)
            }
        }
        #pragma unroll
        for (int c = 0; c < 8; c++) {
            int kx = kxc * 8 + c;
            float ax, ay; upk2(acc[c], ax, ay);
            float sgn = (kx & 1) ? -1.f : 1.f;
            Sraw[c * NSI + z] = make_float2(ax + v0.x + sgn * v60.x,
                                            ay + v0.y + sgn * v60.y);
        }
    }
    __syncthreads();

    // ---- stage 2: cooperative z-fold into fu/fw ----
    for (int i = tid; i < 8 * 60; i += 128) {
        int c = i / 60, zp = i % 60;
        if (zp > 0) {
            float2 a = Sraw[c * NSI + zp];
            float2 b = Sraw[c * NSI + (NSI - zp)];
            fu[i] = make_float2(a.x + b.x, a.y + b.y);
            fw[i] = make_float2(a.y - b.y, a.x - b.x);
        }
    }
    __syncthreads();

    // ---- stage 3: per-thread kz z-DFT (all smem loads are warp-broadcast) ----
    double contrib = 0.0;
    if (tid < NSI) {
        int kz = tid;
        u64 acc2[8];
        #pragma unroll
        for (int c = 0; c < 8; c++) acc2[c] = pk2(0.f, 0.f);
        int idx = kz;    // (kz*zp) % 120, incremental
        for (int zp = 1; zp < 60; zp++) {
            float2 t = tws[idx];
            idx += kz; if (idx >= NSI) idx -= NSI;
            u64 twc = pk2(t.x, t.x);
            u64 tws2 = pk2(-t.y, t.y);
            const u64* pu = (const u64*)fu + zp;     // fu[c*60+zp] as u64
            const u64* pw = (const u64*)fw + zp;
            #pragma unroll
            for (int c = 0; c < 8; c++) {
                fma2(acc2[c], pu[c * 60], twc);
                fma2(acc2[c], pw[c * 60], tws2);
            }
        }
        float sgn = (kz & 1) ? -1.f : 1.f;
        int my = (ky < 60) ? ky : ky - NSI;   // ky==60 -> -60
        float wgt = (ky == 0 || ky == 60) ? 1.0f : 2.0f;
        float fmy = (float)my;
        int mz = (kz < 60) ? kz : kz - NSI;
        float fmz = (float)mz;
        const float twopi = 6.28318530717958647692f;
        #pragma unroll
        for (int c = 0; c < 8; c++) {
            int kx = kxc * 8 + c;
            int mx = (kx < 60) ? kx : kx - NSI;
            float fmx = (float)mx;
            float2 v0 = Sraw[c * NSI];           // z=0 (broadcast)
            float2 v60 = Sraw[c * NSI + 60];     // z=60 (broadcast)
            float ax, ay; upk2(acc2[c], ax, ay);
            float sx = ax + v0.x + sgn * v60.x;
            float sy = ay + v0.y + sgn * v60.y;
            float k0 = twopi * (fmx * g_invc[0] + fmy * g_invc[1] + fmz * g_invc[2]);
            float k1 = twopi * (fmx * g_invc[3] + fmy * g_invc[4] + fmz * g_invc[5]);
            float k2 = twopi * (fmx * g_invc[6] + fmy * g_invc[7] + fmz * g_invc[8]);
            float ksq = k0*k0 + k1*k1 + k2*k2;
            float G = 0.f;
            if (ksq > 0.f)
                G = 4.f * (float)PI_D * expf(-0.5f * ALPHA_F * ALPHA_F * ksq) / ksq;
            G *= wgt;
            contrib += (double)G * ((double)sx * (double)sx +
                                    (double)sy * (double)sy);
        }
    }
    #pragma unroll
    for (int o = 16; o; o >>= 1)
        contrib += __shfl_down_sync(0xffffffffu, contrib, o);
    if ((tid & 31) == 0) red[tid >> 5] = contrib;
    __syncthreads();
    if (tid == 0) {
        double s = red[0] + red[1] + red[2] + red[3];
        atomicAdd(&g_acc[0], s);
    }
}

// ---------------- finalize ----------------
__global__ void final_kernel(float* out) {
    double V  = g_vol;
    double A  = g_acc[0];
    double qs = g_acc[1];
    double q2 = g_acc[2];
    double E = 0.5 * ( A / V
                     - sqrt(2.0 / PI_D) / (double)ALPHA_F * q2
                     - 2.0 * PI_D * (double)(ALPHA_F * ALPHA_F) * qs * qs / V );
    out[0] = (float)E;
}

extern "C" void kernel_launch(void* const* d_in, const int* in_sizes, int n_in,
                              void* d_out, int out_size) {
    const float* coords  = (const float*)d_in[0];
    const float* box     = (const float*)d_in[1];
    const float* charges = (const float*)d_in[2];
    int n = in_sizes[2];   // N_ATOMS

    setup_kernel<<<1, 128>>>(box);
    zero_mesh_kernel<<<(NS3/4 + 255)/256, 256>>>();
    spread_kernel<<<(n + 127)/128, 128>>>(coords, charges, n);
    passA_kernel<<<dim3(8, NSI), 128>>>();
    passBC_kernel<<<dim3(15, RKY), 128>>>();
    final_kernel<<<1, 1>>>((float*)d_out);
}

// round 16
// speedup vs baseline: 1.2321x; 1.0275x over previous
#include <cuda_runtime.h>
#include <math.h>

#define NSI 120
#define NS2 (NSI*NSI)      // 14400
#define NS3 (NSI*NSI*NSI)  // 1728000
#define RKY 61             // ky 0..60 (Hermitian half, y axis)
#define ALPHA_F 1.0f
#define PI_D 3.14159265358979323846

typedef unsigned long long u64;

// ---------------- scratch (static device globals; no allocation) ----------------
__device__ __align__(16) float  g_mesh[NS3];
__device__ __align__(16) float2 g_buf1[NSI*RKY*NSI];   // [(x*61+ky)*120+z]
__device__ float  g_invc[9];   // inv(box)[i][j] at [i*3+j]
__device__ double g_vol;
__device__ double g_acc[3];    // [0]=Sum |S|^2 G, [1]=sum q, [2]=sum q^2
__device__ float2 g_tw[NSI];   // exp(-2*pi*i*t/120)

// ---------------- packed f32x2 helpers ----------------
__device__ __forceinline__ u64 pk2(float x, float y) {
    u64 r; asm("mov.b64 %0, {%1, %2};" : "=l"(r) : "f"(x), "f"(y)); return r;
}
__device__ __forceinline__ void upk2(u64 v, float& x, float& y) {
    asm("mov.b64 {%0, %1}, %2;" : "=f"(x), "=f"(y) : "l"(v));
}
__device__ __forceinline__ void fma2(u64& d, u64 a, u64 b) {
    asm("fma.rn.f32x2 %0, %1, %2, %3;" : "=l"(d) : "l"(a), "l"(b), "l"(d));
}

// ---------------- vector global reductions (sm_90+) ----------------
__device__ __forceinline__ void red2(float* p, float a, float b) {
    asm volatile("red.global.add.v2.f32 [%0], {%1, %2};"
                 :: "l"(p), "f"(a), "f"(b) : "memory");
}
__device__ __forceinline__ void red4(float* p, float a, float b, float c, float d) {
    asm volatile("red.global.add.v4.f32 [%0], {%1, %2, %3, %4};"
                 :: "l"(p), "f"(a), "f"(b), "f"(c), "f"(d) : "memory");
}

// ---------------- zero mesh + setup (merged: block 0 also does constants) -----
__global__ void zs_kernel(const float* __restrict__ box) {
    int tid = threadIdx.x;
    if (blockIdx.x == 0) {
        if (tid < NSI) {
            double ang = -2.0 * PI_D * (double)tid / (double)NSI;
            g_tw[tid] = make_float2((float)cos(ang), (float)sin(ang));
        }
        if (tid == 0) {
            double b[9];
            for (int i = 0; i < 9; i++) b[i] = (double)box[i];
            double c00 =  (b[4]*b[8] - b[5]*b[7]);
            double c01 = -(b[3]*b[8] - b[5]*b[6]);
            double c02 =  (b[3]*b[7] - b[4]*b[6]);
            double c10 = -(b[1]*b[8] - b[2]*b[7]);
            double c11 =  (b[0]*b[8] - b[2]*b[6]);
            double c12 = -(b[0]*b[7] - b[1]*b[6]);
            double c20 =  (b[1]*b[5] - b[2]*b[4]);
            double c21 = -(b[0]*b[5] - b[2]*b[3]);
            double c22 =  (b[0]*b[4] - b[1]*b[3]);
            double det = b[0]*c00 + b[1]*c01 + b[2]*c02;
            g_invc[0] = (float)(c00/det); g_invc[1] = (float)(c10/det); g_invc[2] = (float)(c20/det);
            g_invc[3] = (float)(c01/det); g_invc[4] = (float)(c11/det); g_invc[5] = (float)(c21/det);
            g_invc[6] = (float)(c02/det); g_invc[7] = (float)(c12/det); g_invc[8] = (float)(c22/det);
            g_vol = fabs(det);
            g_acc[0] = 0.0; g_acc[1] = 0.0; g_acc[2] = 0.0;
        }
    }
    int i = blockIdx.x * blockDim.x + tid;
    float4* p = (float4*)g_mesh;
    if (i < NS3/4) p[i] = make_float4(0.f, 0.f, 0.f, 0.f);
}

// ---------------- order-6 Lagrange weights, nodes t_j = j - 2.5 ----------------
__device__ __forceinline__ void lag6(float x, float* w) {
    float d0 = x + 2.5f, d1 = x + 1.5f, d2 = x + 0.5f;
    float d3 = x - 0.5f, d4 = x - 1.5f, d5 = x - 2.5f;
    float p1 = d0, p2 = p1*d1, p3 = p2*d2, p4 = p3*d3, p5 = p4*d4;
    float s4 = d5, s3 = s4*d4, s2 = s3*d3, s1 = s2*d2, s0 = s1*d1;
    w[0] = s0      * (-1.f/120.f);
    w[1] = p1 * s1 * ( 1.f/24.f);
    w[2] = p2 * s2 * (-1.f/12.f);
    w[3] = p3 * s3 * ( 1.f/12.f);
    w[4] = p4 * s4 * (-1.f/24.f);
    w[5] = p5      * ( 1.f/120.f);
}

__device__ __forceinline__ int wrap120(int v) {
    return (v < 0) ? v + NSI : ((v >= NSI) ? v - NSI : v);
}

// ---------------- spread: one thread per atom, vector reductions --------------
__global__ void spread_kernel(const float* __restrict__ coords,
                              const float* __restrict__ charges, int n) {
    int i = blockIdx.x * blockDim.x + threadIdx.x;
    float q = 0.f;
    float wx[6], wy[6], wz[6];
    int gx[6], gy[6], gz[6];
    int z0w = 0;
    bool act = (i < n);
    if (act) {
        float c0 = coords[3*i], c1 = coords[3*i+1], c2 = coords[3*i+2];
        q = charges[i];
        float fx = c0*g_invc[0] + c1*g_invc[3] + c2*g_invc[6];
        float fy = c0*g_invc[1] + c1*g_invc[4] + c2*g_invc[7];
        float fz = c0*g_invc[2] + c1*g_invc[5] + c2*g_invc[8];
        float px = fx * (float)NSI, py = fy * (float)NSI, pz = fz * (float)NSI;
        float i0x = floorf(px), i0y = floorf(py), i0z = floorf(pz);
        lag6(px - i0x - 0.5f, wx);
        lag6(py - i0y - 0.5f, wy);
        lag6(pz - i0z - 0.5f, wz);
        int ix = (int)i0x, iy = (int)i0y, iz = (int)i0z;
        #pragma unroll
        for (int a = 0; a < 6; a++) {
            gx[a] = wrap120(ix + a - 2);
            gy[a] = wrap120(iy + a - 2);
            gz[a] = wrap120(iz + a - 2);
        }
        z0w = gz[0];
    }
    double dq = (double)q, dq2 = (double)q * (double)q;
    #pragma unroll
    for (int o = 16; o; o >>= 1) {
        dq  += __shfl_down_sync(0xffffffffu, dq,  o);
        dq2 += __shfl_down_sync(0xffffffffu, dq2, o);
    }
    if ((threadIdx.x & 31) == 0) {
        atomicAdd(&g_acc[1], dq);
        atomicAdd(&g_acc[2], dq2);
    }
    if (!act) return;

    bool zcontig = (z0w <= NSI - 6);    // 6 consecutive z cells, no wrap
    int zmod = z0w & 3;                 // uniform over the whole atom

    #pragma unroll
    for (int a = 0; a < 6; a++) {
        int rowx = gx[a] * NS2;
        float wq = wx[a] * q;
        #pragma unroll
        for (int b = 0; b < 6; b++) {
            int row = rowx + gy[b] * NSI;
            float wxy = wq * wy[b];
            float v0 = wxy*wz[0], v1 = wxy*wz[1], v2 = wxy*wz[2];
            float v3 = wxy*wz[3], v4 = wxy*wz[4], v5 = wxy*wz[5];
            if (zcontig) {
                float* p = g_mesh + row + z0w;
                if (zmod == 0) {
                    red4(p, v0, v1, v2, v3);
                    red2(p + 4, v4, v5);
                } else if (zmod == 2) {
                    red2(p, v0, v1);
                    red4(p + 2, v2, v3, v4, v5);
                } else if (zmod == 3) {
                    atomicAdd(p, v0);
                    red4(p + 1, v1, v2, v3, v4);
                    atomicAdd(p + 5, v5);
                } else { // zmod == 1: zero-padded aligned pair (z0<=113 here)
                    red4(p - 1, 0.f, v0, v1, v2);
                    red4(p + 3, v3, v4, v5, 0.f);
                }
            } else {
                atomicAdd(&g_mesh[row + gz[0]], v0);
                atomicAdd(&g_mesh[row + gz[1]], v1);
                atomicAdd(&g_mesh[row + gz[2]], v2);
                atomicAdd(&g_mesh[row + gz[3]], v3);
                atomicAdd(&g_mesh[row + gz[4]], v4);
                atomicAdd(&g_mesh[row + gz[5]], v5);
            }
        }
    }
}

// ---------------- pass A: DFT along y (real -> complex), ky in [0,60] ---------
// exact champion version. grid (8 ky-chunks of 8, 120 x), block 128.
__global__ void __launch_bounds__(128) passA_kernel() {
    __shared__ __align__(16) u64 tw8[60 * 8];   // packed (cos,sin); y=0 unused
    int kyc = blockIdx.x;
    int x   = blockIdx.y;
    int tid = threadIdx.x;
    for (int i = tid; i < 60 * 8; i += 128) {
        int y = i >> 3, c = i & 7;
        int ky = kyc * 8 + c;
        float2 t = g_tw[(ky * y) % NSI];
        tw8[i] = pk2(t.x, t.y);
    }
    __syncthreads();
    if (tid < NSI) {
        int z = tid;
        const float* mrow = g_mesh + x * NS2 + z;
        u64 acc[8];
        #pragma unroll
        for (int c = 0; c < 8; c++) acc[c] = pk2(0.f, 0.f);
        float v0  = mrow[0];
        float v60 = mrow[60 * NSI];
        for (int yp = 1; yp < 60; yp++) {
            float a = mrow[yp * NSI];
            float b = mrow[(NSI - yp) * NSI];
            u64 uw = pk2(a + b, a - b);
            const ulonglong2* t = (const ulonglong2*)&tw8[yp * 8];
            #pragma unroll
            for (int j = 0; j < 4; j++) {
                ulonglong2 tv = t[j];
                fma2(acc[2*j  ], uw, tv.x);
                fma2(acc[2*j+1], uw, tv.y);
            }
        }
        #pragma unroll
        for (int c = 0; c < 8; c++) {
            int ky = kyc * 8 + c;
            if (ky < RKY) {
                float ax, ay; upk2(acc[c], ax, ay);
                float sgn = (ky & 1) ? -1.f : 1.f;
                float sx = ax + v0 + sgn * v60;
                g_buf1[(x * RKY + ky) * NSI + z] = make_float2(sx, ay);
            }
        }
    }
}

// ---------------- fused pass B+C: x-DFT then in-block z-DFT + G|S|^2 reduce ---
// grid (15 kx-chunks of 8, 61 ky), block 128; thread = z for x-DFT, = kz after.
__global__ void __launch_bounds__(128) passBC_kernel() {
    __shared__ __align__(16) u64 tw8[60 * 8 * 2];    // per (x,kx): (c,c), (-s,s)
    __shared__ __align__(8)  float2 Sraw[8 * NSI];   // [c*120 + z]
    __shared__ __align__(8)  float2 fu[8 * 60];      // (ax+bx, ay+by) per (c,zp)
    __shared__ __align__(8)  float2 fw[8 * 60];      // (ay-by, ax-bx) per (c,zp)
    __shared__ __align__(8)  float2 tws[NSI];        // g_tw copy
    __shared__ double red[4];
    int kxc = blockIdx.x;
    int ky  = blockIdx.y;
    int tid = threadIdx.x;
    for (int i = tid; i < 60 * 8; i += 128) {
        int xv = i >> 3, c = i & 7;
        int kx = kxc * 8 + c;
        float2 t = g_tw[(kx * xv) % NSI];
        tw8[2*i]   = pk2(t.x, t.x);
        tw8[2*i+1] = pk2(-t.y, t.y);
    }
    if (tid < NSI) tws[tid] = g_tw[tid];
    __syncthreads();

    // ---- stage 1: x-DFT (exact champion passB arithmetic), result -> Sraw ----
    if (tid < NSI) {
        int z = tid;
        u64 acc[8];
        #pragma unroll
        for (int c = 0; c < 8; c++) acc[c] = pk2(0.f, 0.f);
        const float2* col = g_buf1 + ky * NSI + z;   // stride over x = RKY*NSI
        float2 v0  = col[0];
        float2 v60 = col[60 * (RKY * NSI)];
        for (int xp = 1; xp < 60; xp++) {
            float2 a = col[xp * (RKY * NSI)];
            float2 b = col[(NSI - xp) * (RKY * NSI)];
            u64 u1 = pk2(a.x + b.x, a.y + b.y);      // (ux, uy)
            u64 u2 = pk2(a.y - b.y, a.x - b.x);      // (wy, wx)
            const ulonglong2* t = (const ulonglong2*)&tw8[xp * 16];
            #pragma unroll
            for (int c = 0; c < 8; c++) {
                ulonglong2 tv = t[c];
                fma2(acc[c], u1, tv.x);   // += (c*ux, c*uy)
                fma2(acc[c], u2, tv.y);   // += (-s*wy, s*wx)
            }
        }
        #pragma unroll
        for (int c = 0; c < 8; c++) {
            int kx = kxc * 8 + c;
            float ax, ay; upk2(acc[c], ax, ay);
            float sgn = (kx & 1) ? -1.f : 1.f;
            Sraw[c * NSI + z] = make_float2(ax + v0.x + sgn * v60.x,
                                            ay + v0.y + sgn * v60.y);
        }
    }
    __syncthreads();

    // ---- stage 2: cooperative z-fold into fu/fw ----
    for (int i = tid; i < 8 * 60; i += 128) {
        int c = i / 60, zp = i % 60;
        if (zp > 0) {
            float2 a = Sraw[c * NSI + zp];
            float2 b = Sraw[c * NSI + (NSI - zp)];
            fu[i] = make_float2(a.x + b.x, a.y + b.y);
            fw[i] = make_float2(a.y - b.y, a.x - b.x);
        }
    }
    __syncthreads();

    // ---- stage 3: per-thread kz z-DFT (all smem loads are warp-broadcast) ----
    double contrib = 0.0;
    if (tid < NSI) {
        int kz = tid;
        u64 acc2[8];
        #pragma unroll
        for (int c = 0; c < 8; c++) acc2[c] = pk2(0.f, 0.f);
        int idx = kz;    // (kz*zp) % 120, incremental
        for (int zp = 1; zp < 60; zp++) {
            float2 t = tws[idx];
            idx += kz; if (idx >= NSI) idx -= NSI;
            u64 twc = pk2(t.x, t.x);
            u64 tws2 = pk2(-t.y, t.y);
            const u64* pu = (const u64*)fu + zp;     // fu[c*60+zp] as u64
            const u64* pw = (const u64*)fw + zp;
            #pragma unroll
            for (int c = 0; c < 8; c++) {
                fma2(acc2[c], pu[c * 60], twc);
                fma2(acc2[c], pw[c * 60], tws2);
            }
        }
        float sgn = (kz & 1) ? -1.f : 1.f;
        int my = (ky < 60) ? ky : ky - NSI;   // ky==60 -> -60
        float wgt = (ky == 0 || ky == 60) ? 1.0f : 2.0f;
        float fmy = (float)my;
        int mz = (kz < 60) ? kz : kz - NSI;
        float fmz = (float)mz;
        const float twopi = 6.28318530717958647692f;
        // hoist (fmy,fmz) part of k; add fmx contribution per c
        float b0 = fmy * g_invc[1] + fmz * g_invc[2];
        float b1 = fmy * g_invc[4] + fmz * g_invc[5];
        float b2 = fmy * g_invc[7] + fmz * g_invc[8];
        #pragma unroll
        for (int c = 0; c < 8; c++) {
            int kx = kxc * 8 + c;
            int mx = (kx < 60) ? kx : kx - NSI;
            float fmx = (float)mx;
            float2 v0 = Sraw[c * NSI];           // z=0 (broadcast)
            float2 v60 = Sraw[c * NSI + 60];     // z=60 (broadcast)
            float ax, ay; upk2(acc2[c], ax, ay);
            float sx = ax + v0.x + sgn * v60.x;
            float sy = ay + v0.y + sgn * v60.y;
            float k0 = twopi * (fmx * g_invc[0] + b0);
            float k1 = twopi * (fmx * g_invc[3] + b1);
            float k2 = twopi * (fmx * g_invc[6] + b2);
            float ksq = k0*k0 + k1*k1 + k2*k2;
            float G = 0.f;
            if (ksq > 0.f)
                G = 4.f * (float)PI_D * expf(-0.5f * ALPHA_F * ALPHA_F * ksq) / ksq;
            G *= wgt;
            contrib += (double)G * ((double)sx * (double)sx +
                                    (double)sy * (double)sy);
        }
    }
    #pragma unroll
    for (int o = 16; o; o >>= 1)
        contrib += __shfl_down_sync(0xffffffffu, contrib, o);
    if ((tid & 31) == 0) red[tid >> 5] = contrib;
    __syncthreads();
    if (tid == 0) {
        double s = red[0] + red[1] + red[2] + red[3];
        atomicAdd(&g_acc[0], s);
    }
}

// ---------------- finalize ----------------
__global__ void final_kernel(float* out) {
    double V  = g_vol;
    double A  = g_acc[0];
    double qs = g_acc[1];
    double q2 = g_acc[2];
    double E = 0.5 * ( A / V
                     - sqrt(2.0 / PI_D) / (double)ALPHA_F * q2
                     - 2.0 * PI_D * (double)(ALPHA_F * ALPHA_F) * qs * qs / V );
    out[0] = (float)E;
}

extern "C" void kernel_launch(void* const* d_in, const int* in_sizes, int n_in,
                              void* d_out, int out_size) {
    const float* coords  = (const float*)d_in[0];
    const float* box     = (const float*)d_in[1];
    const float* charges = (const float*)d_in[2];
    int n = in_sizes[2];   // N_ATOMS

    zs_kernel<<<(NS3/4 + 255)/256, 256>>>(box);
    spread_kernel<<<(n + 127)/128, 128>>>(coords, charges, n);
    passA_kernel<<<dim3(8, NSI), 128>>>();
    passBC_kernel<<<dim3(15, RKY), 128>>>();
    final_kernel<<<1, 1>>>((float*)d_out);
}